// round 5
// baseline (speedup 1.0000x reference)
#include <cuda_runtime.h>
#include <math.h>

#define TAU 0.07f
#define EPSN 1e-12f

constexpr int B_   = 4;
constexpr int C_   = 256;
constexpr int K_   = 19;
constexpr int HW   = 65536;          // H*W = 256*256
constexpr int P    = B_ * HW;        // 262144 pixels
constexpr int TILE_Q = 64;           // pixels per tile in kA
constexpr int NTILES = P / TILE_Q;   // 4096
constexpr int NBLK_A = 296;          // 2 per SM
constexpr int NBLK_C = 512;          // 512 * 256 threads * 2 px = P
constexpr int KC   = K_ * C_;        // 4864
constexpr int TSTRIDE = 68;          // padded smem tile row stride (floats)

// ---- scratch (static __device__, no allocation) ----
__device__ float g_part[(size_t)NBLK_A * KC];  // per-block k0 partials
__device__ float g_npos[P];                    // positives per pixel
__device__ float g_k0n[KC];                    // normalized prototypes
__device__ float g_normk[K_];                  // k0n·k0 per class
__device__ int   g_nposblk[NBLK_A];            // per-block positive counts
__device__ float g_lsepart[NBLK_C];            // per-block npos*lse partials

// ---- f32x2 packed-FMA helpers (exact fp32, 2 lanes per issue slot) ----
__device__ __forceinline__ void fma2(unsigned long long &acc,
                                     unsigned long long a,
                                     unsigned long long b) {
    asm("fma.rn.f32x2 %0, %1, %2, %3;" : "=l"(acc) : "l"(a), "l"(b), "l"(acc));
}
__device__ __forceinline__ float2 unpack2(unsigned long long v) {
    float2 r;
    asm("mov.b64 {%0, %1}, %2;" : "=f"(r.x), "=f"(r.y) : "l"(v));
    return r;
}
__device__ __forceinline__ unsigned long long pack2(float lo, float hi) {
    unsigned long long r;
    asm("mov.b64 %0, {%1, %2};" : "=l"(r) : "f"(lo), "f"(hi));
    return r;
}

// ============================================================
// Kernel A: fused rnorm + mask + k0 partial accumulation
//   grid 296 x 256 threads, dynamic smem ~75.5KB
// ============================================================
extern "C" __global__ void __launch_bounds__(256, 2)
kA(const float* __restrict__ feat, const float* __restrict__ gt)
{
    extern __shared__ float sm[];
    float* s_tile = sm;                         // [256][68]
    float* s_wk   = sm + C_ * TSTRIDE;          // [19][64]  (rn or 0 per (k,q))
    float* s_sq   = s_wk + K_ * TILE_Q;         // [4][64] ssq partials

    const int tid  = threadIdx.x;
    const int blk  = blockIdx.x;
    const int qof  = tid & 63;
    const int cgrp = tid >> 6;

    unsigned long long acc[K_];
#pragma unroll
    for (int k = 0; k < K_; k++) acc[k] = 0ull;
    int np_acc = 0;

    for (int t = blk; t < NTILES; t += NBLK_A) {
        const int p0  = t * TILE_Q;
        const int b   = p0 >> 16;
        const int hw0 = p0 & 65535;
        const float* fb = feat + (size_t)b * C_ * HW + hw0;

        __syncthreads();  // protect smem from previous tile's compute

        // ---- stage tile (coalesced) + sumsq partial ----
        float ssql = 0.f;
#pragma unroll 4
        for (int i = 0; i < (C_ * TILE_Q) / 256; i++) {   // 64 iterations
            const int c = cgrp + i * 4;
            const float v = __ldg(fb + (size_t)c * HW + qof);
            s_tile[c * TSTRIDE + qof] = v;
            ssql = fmaf(v, v, ssql);
        }
        s_sq[cgrp * 64 + qof] = ssql;
        __syncthreads();

        // ---- rnorm + gt mask -> weights (64 threads) ----
        if (tid < TILE_Q) {
            const int q = tid;
            const float ssq = s_sq[q] + s_sq[64 + q] + s_sq[128 + q] + s_sq[192 + q];
            const float rn  = 1.0f / fmaxf(sqrtf(ssq), EPSN);
            const float* gb = gt + (size_t)b * K_ * HW + hw0 + q;
            int np = 0;
#pragma unroll
            for (int k = 0; k < K_; k++) {
                const float g = __ldg(gb + (size_t)k * HW);
                const bool pos = (g == 1.0f);
                s_wk[k * TILE_Q + q] = pos ? rn : 0.f;
                np += pos ? 1 : 0;
            }
            g_npos[p0 + q] = (float)np;
            np_acc += np;
        }
        __syncthreads();

        // ---- compute: thread owns channel c = tid; packed FFMA2 inner ----
        const float* trow = s_tile + tid * TSTRIDE;
#pragma unroll 4
        for (int q4 = 0; q4 < TILE_Q / 4; q4++) {
            const ulonglong2 v = *(const ulonglong2*)(trow + q4 * 4);
#pragma unroll
            for (int k = 0; k < K_; k++) {
                const ulonglong2 w = *(const ulonglong2*)(s_wk + k * TILE_Q + q4 * 4);
                fma2(acc[k], v.x, w.x);
                fma2(acc[k], v.y, w.y);
            }
        }
    }

    // ---- emit per-block partials (deterministic, no atomics) ----
#pragma unroll
    for (int k = 0; k < K_; k++) {
        const float2 a = unpack2(acc[k]);
        g_part[(size_t)blk * KC + k * C_ + tid] = a.x + a.y;
    }

    __syncthreads();
    int* s_int = (int*)s_sq;
    if (tid < TILE_Q) s_int[tid] = np_acc;
    __syncthreads();
    if (tid == 0) {
        int s = 0;
        for (int i = 0; i < TILE_Q; i++) s += s_int[i];
        g_nposblk[blk] = s;
    }
}

// ============================================================
// Kernel B: reduce k0 partials -> k0n, per-class norms
// ============================================================
extern "C" __global__ void kB()
{
    const int k = blockIdx.x;
    const int c = threadIdx.x;
    float v = 0.f;
    for (int b = 0; b < NBLK_A; b++)
        v += g_part[(size_t)b * KC + k * C_ + c];

    __shared__ float red[256];
    red[c] = v * v;
    __syncthreads();
    for (int s = 128; s > 0; s >>= 1) {
        if (c < s) red[c] += red[c + s];
        __syncthreads();
    }
    const float ssq = red[0];
    const float inv = 1.0f / fmaxf(sqrtf(ssq), EPSN);
    g_k0n[k * C_ + c] = v * inv;
    if (c == 0) g_normk[k] = ssq * inv;   // = k0n . k0
}

// ============================================================
// Kernel C: per-pixel logits + logsumexp (2 pixels/thread, FFMA2)
//   grid 512 x 256 threads
// ============================================================
extern "C" __global__ void __launch_bounds__(256)
kC(const float* __restrict__ feat)
{
    // prototype weights duplicated as (w,w) 64-bit pairs: [c][k] padded to 20
    __shared__ unsigned long long s_w2[C_ * 20];
    const int tid = threadIdx.x;
    for (int idx = tid; idx < KC; idx += 256) {
        const int k = idx >> 8;      // idx / 256
        const int c = idx & 255;
        const float w = g_k0n[idx];
        s_w2[c * 20 + k] = pack2(w, w);
    }
    for (int c = tid; c < C_; c += 256) s_w2[c * 20 + 19] = 0ull;
    __syncthreads();

    const int p0 = blockIdx.x * 512 + tid * 2;   // 2 adjacent pixels
    const int b  = p0 >> 16;
    const int hw = p0 & 65535;
    const float* fp = feat + (size_t)b * C_ * HW + hw;

    unsigned long long s[20];
#pragma unroll
    for (int k = 0; k < 20; k++) s[k] = 0ull;
    unsigned long long ssq2 = 0ull;

#pragma unroll 4
    for (int c = 0; c < C_; c++) {
        const unsigned long long v2 = *(const unsigned long long*)(fp + (size_t)c * HW);
        fma2(ssq2, v2, v2);
        const ulonglong2* row = (const ulonglong2*)(s_w2 + c * 20);
#pragma unroll
        for (int j = 0; j < 10; j++) {
            const ulonglong2 w = row[j];
            fma2(s[2 * j + 0], v2, w.x);
            fma2(s[2 * j + 1], v2, w.y);
        }
    }

    const float2 sq = unpack2(ssq2);
    const float rnt0 = 1.0f / (fmaxf(sqrtf(sq.x), EPSN) * TAU);
    const float rnt1 = 1.0f / (fmaxf(sqrtf(sq.y), EPSN) * TAU);

    float l0[K_], l1[K_];
    float mx0 = -3.4e38f, mx1 = -3.4e38f;
#pragma unroll
    for (int k = 0; k < K_; k++) {
        const float2 d = unpack2(s[k]);
        l0[k] = d.x * rnt0;  mx0 = fmaxf(mx0, l0[k]);
        l1[k] = d.y * rnt1;  mx1 = fmaxf(mx1, l1[k]);
    }
    float sum0 = 0.f, sum1 = 0.f;
#pragma unroll
    for (int k = 0; k < K_; k++) {
        sum0 += expf(l0[k] - mx0);
        sum1 += expf(l1[k] - mx1);
    }
    const float lse0 = mx0 + logf(sum0);
    const float lse1 = mx1 + logf(sum1);

    const float contrib = g_npos[p0] * lse0 + g_npos[p0 + 1] * lse1;

    __shared__ float red[256];
    red[tid] = contrib;
    __syncthreads();
    for (int st = 128; st > 0; st >>= 1) {
        if (tid < st) red[tid] += red[tid + st];
        __syncthreads();
    }
    if (tid == 0) g_lsepart[blockIdx.x] = red[0];
}

// ============================================================
// Kernel D: final scalar loss
// ============================================================
extern "C" __global__ void kD(float* __restrict__ out)
{
    __shared__ float red[256];
    __shared__ int   redi[256];
    const int tid = threadIdx.x;

    float a = 0.f;
    for (int i = tid; i < NBLK_C; i += 256) a += g_lsepart[i];
    float nk = 0.f;
    if (tid < K_) nk = g_normk[tid];
    int np = 0;
    for (int i = tid; i < NBLK_A; i += 256) np += g_nposblk[i];

    red[tid]  = a - nk * (1.0f / TAU);
    redi[tid] = np;
    __syncthreads();
    for (int s = 128; s > 0; s >>= 1) {
        if (tid < s) { red[tid] += red[tid + s]; redi[tid] += redi[tid + s]; }
        __syncthreads();
    }
    if (tid == 0) out[0] = red[0] / (float)redi[0];
}

// ============================================================
// launch
// ============================================================
extern "C" void kernel_launch(void* const* d_in, const int* in_sizes, int n_in,
                              void* d_out, int out_size)
{
    const float* feat = (const float*)d_in[0];
    const float* gt   = (const float*)d_in[1];
    float* out        = (float*)d_out;

    const int smemA = (C_ * TSTRIDE + K_ * TILE_Q + 256) * (int)sizeof(float); // 75520
    cudaFuncSetAttribute(kA, cudaFuncAttributeMaxDynamicSharedMemorySize, smemA);

    kA<<<NBLK_A, 256, smemA>>>(feat, gt);
    kB<<<K_, 256>>>();
    kC<<<NBLK_C, 256>>>(feat);
    kD<<<1, 256>>>(out);
}

// round 7
// speedup vs baseline: 1.3764x; 1.3764x over previous
#include <cuda_runtime.h>
#include <math.h>

#define TAU 0.07f
#define EPSN 1e-12f

constexpr int B_   = 4;
constexpr int C_   = 256;
constexpr int K_   = 19;
constexpr int HW   = 65536;          // 256*256
constexpr int P    = B_ * HW;        // 262144
constexpr int TILE_Q = 64;
constexpr int NTILES = P / TILE_Q;   // 4096
constexpr int NBLK_A = 148;          // 1 CTA/SM (big smem)
constexpr int NBLK_C = 1024;
constexpr int KC   = K_ * C_;        // 4864
constexpr int TSTRIDE = 68;          // padded tile row stride (floats)

// ---- scratch (static __device__, no allocation) ----
__device__ float  g_part[(size_t)NBLK_A * KC];
__device__ float2 g_npr[P];          // (npos, rn) per pixel
__device__ float  g_k0n[KC];
__device__ float  g_normk[K_];
__device__ int    g_nposblk[NBLK_A];
__device__ float  g_lsepart[NBLK_C];

// ---- cp.async helpers ----
__device__ __forceinline__ unsigned smem_u32(const void* p) {
    return (unsigned)__cvta_generic_to_shared(p);
}
__device__ __forceinline__ void cp4(unsigned dst, const void* src) {
    asm volatile("cp.async.ca.shared.global [%0], [%1], 4;\n" :: "r"(dst), "l"(src));
}
__device__ __forceinline__ void cp_commit() { asm volatile("cp.async.commit_group;\n" ::: "memory"); }
__device__ __forceinline__ void cp_wait0()  { asm volatile("cp.async.wait_group 0;\n" ::: "memory"); }

// ============================================================
// Kernel A: pipelined rnorm + mask + k0 partial accumulation
//   grid 148 x 256 threads, ~150KB dynamic smem, 1 CTA/SM
//   per tile: issue cp.async(t+1) -> compute(t) -> wait -> ssq -> mask
// ============================================================
__device__ __forceinline__ void kA_issue(const float* __restrict__ feat,
                                         const float* __restrict__ gt,
                                         float* buf, float* s_gt,
                                         int t, int tid, int qof, int cgrp)
{
    const int p0  = t * TILE_Q;
    const int b   = p0 >> 16;
    const int hw0 = p0 & 65535;
    const float* fb = feat + (size_t)b * C_ * HW + hw0 + qof;
#pragma unroll 8
    for (int i = 0; i < 64; i++) {
        const int c = cgrp + i * 4;
        cp4(smem_u32(buf + c * TSTRIDE + qof), fb + (size_t)c * HW);
    }
    const float* gb = gt + (size_t)b * K_ * HW + hw0;
    for (int idx = tid; idx < K_ * TILE_Q; idx += 256) {
        const int k = idx >> 6;
        const int q = idx & 63;
        cp4(smem_u32(s_gt + idx), gb + (size_t)k * HW + q);
    }
    cp_commit();
}

extern "C" __global__ void __launch_bounds__(256, 1)
kA(const float* __restrict__ feat, const float* __restrict__ gt)
{
    extern __shared__ float sm[];
    float* buf0 = sm;                           // [256][68]
    float* buf1 = sm + C_ * TSTRIDE;            // [256][68]
    float* s_wk = sm + 2 * C_ * TSTRIDE;        // [19][64]
    float* s_sq = s_wk + K_ * TILE_Q;           // [256]
    float* s_gt = s_sq + 256;                   // [19][64]

    const int tid  = threadIdx.x;
    const int blk  = blockIdx.x;
    const int qof  = tid & 63;
    const int cgrp = tid >> 6;

    float acc[K_];
#pragma unroll
    for (int k = 0; k < K_; k++) acc[k] = 0.f;
    int np_acc = 0;

    // ---------------- prolog: stage first tile ----------------
    int t = blk;
    kA_issue(feat, gt, buf0, s_gt, t, tid, qof, cgrp);
    cp_wait0();
    __syncthreads();

    // ssq for first tile (4 threads per pixel, 4-way ILP)
    {
        const float* col = buf0 + (cgrp * 64) * TSTRIDE + qof;
        float a0 = 0.f, a1 = 0.f, a2 = 0.f, a3 = 0.f;
#pragma unroll
        for (int cc = 0; cc < 64; cc += 4) {
            const float v0 = col[(cc + 0) * TSTRIDE];
            const float v1 = col[(cc + 1) * TSTRIDE];
            const float v2 = col[(cc + 2) * TSTRIDE];
            const float v3 = col[(cc + 3) * TSTRIDE];
            a0 = fmaf(v0, v0, a0); a1 = fmaf(v1, v1, a1);
            a2 = fmaf(v2, v2, a2); a3 = fmaf(v3, v3, a3);
        }
        s_sq[cgrp * 64 + qof] = (a0 + a1) + (a2 + a3);
    }
    __syncthreads();
    if (tid < TILE_Q) {
        const int q = tid;
        const float ssq = s_sq[q] + s_sq[64 + q] + s_sq[128 + q] + s_sq[192 + q];
        const float rn  = 1.0f / fmaxf(sqrtf(ssq), EPSN);
        int np = 0;
#pragma unroll
        for (int k = 0; k < K_; k++) {
            const bool pos = (s_gt[k * TILE_Q + q] == 1.0f);
            s_wk[k * TILE_Q + q] = pos ? rn : 0.f;
            np += pos ? 1 : 0;
        }
        g_npr[t * TILE_Q + q] = make_float2((float)np, rn);
        np_acc += np;
    }
    __syncthreads();

    // ---------------- pipelined main loop ----------------
    int bsel = 0;
    while (true) {
        const int tn = t + NBLK_A;
        const bool hn = (tn < NTILES);
        float* cur = bsel ? buf1 : buf0;
        float* nxt = bsel ? buf0 : buf1;

        if (hn) kA_issue(feat, gt, nxt, s_gt, tn, tid, qof, cgrp);

        // compute on current tile: thread owns channel c = tid
        const float* trow = cur + tid * TSTRIDE;
#pragma unroll 4
        for (int q4 = 0; q4 < TILE_Q / 4; q4++) {
            const float4 v = *(const float4*)(trow + q4 * 4);
#pragma unroll
            for (int k = 0; k < K_; k++) {
                const float4 w = *(const float4*)(s_wk + k * TILE_Q + q4 * 4);
                acc[k] = fmaf(v.x, w.x, acc[k]);
                acc[k] = fmaf(v.y, w.y, acc[k]);
                acc[k] = fmaf(v.z, w.z, acc[k]);
                acc[k] = fmaf(v.w, w.w, acc[k]);
            }
        }
        if (!hn) break;

        cp_wait0();
        __syncthreads();

        // ssq(t+1) from staged tile
        {
            const float* col = nxt + (cgrp * 64) * TSTRIDE + qof;
            float a0 = 0.f, a1 = 0.f, a2 = 0.f, a3 = 0.f;
#pragma unroll
            for (int cc = 0; cc < 64; cc += 4) {
                const float v0 = col[(cc + 0) * TSTRIDE];
                const float v1 = col[(cc + 1) * TSTRIDE];
                const float v2 = col[(cc + 2) * TSTRIDE];
                const float v3 = col[(cc + 3) * TSTRIDE];
                a0 = fmaf(v0, v0, a0); a1 = fmaf(v1, v1, a1);
                a2 = fmaf(v2, v2, a2); a3 = fmaf(v3, v3, a3);
            }
            s_sq[cgrp * 64 + qof] = (a0 + a1) + (a2 + a3);
        }
        __syncthreads();

        // mask(t+1): build weights
        if (tid < TILE_Q) {
            const int q = tid;
            const float ssq = s_sq[q] + s_sq[64 + q] + s_sq[128 + q] + s_sq[192 + q];
            const float rn  = 1.0f / fmaxf(sqrtf(ssq), EPSN);
            int np = 0;
#pragma unroll
            for (int k = 0; k < K_; k++) {
                const bool pos = (s_gt[k * TILE_Q + q] == 1.0f);
                s_wk[k * TILE_Q + q] = pos ? rn : 0.f;
                np += pos ? 1 : 0;
            }
            g_npr[tn * TILE_Q + q] = make_float2((float)np, rn);
            np_acc += np;
        }
        __syncthreads();

        t = tn;
        bsel ^= 1;
    }

    // ---- emit per-block partials (deterministic) ----
#pragma unroll
    for (int k = 0; k < K_; k++)
        g_part[(size_t)blk * KC + k * C_ + tid] = acc[k];

    __syncthreads();
    int* s_int = (int*)s_sq;
    if (tid < TILE_Q) s_int[tid] = np_acc;
    __syncthreads();
    if (tid == 0) {
        int s = 0;
        for (int i = 0; i < TILE_Q; i++) s += s_int[i];
        g_nposblk[blk] = s;
    }
}

// ============================================================
// Kernel B: reduce k0 partials -> k0n, per-class norms
// ============================================================
extern "C" __global__ void kB()
{
    const int k = blockIdx.x;
    const int c = threadIdx.x;
    float v = 0.f;
#pragma unroll 4
    for (int b = 0; b < NBLK_A; b++)
        v += g_part[(size_t)b * KC + k * C_ + c];

    __shared__ float red[256];
    red[c] = v * v;
    __syncthreads();
    for (int s = 128; s > 0; s >>= 1) {
        if (c < s) red[c] += red[c + s];
        __syncthreads();
    }
    const float ssq = red[0];
    const float inv = 1.0f / fmaxf(sqrtf(ssq), EPSN);
    g_k0n[k * C_ + c] = v * inv;
    if (c == 0) g_normk[k] = ssq * inv;   // = k0n . k0
}

// ============================================================
// Kernel C: per-pixel logits + logsumexp (rn reused from kA)
//   grid 1024 x 256 threads, 1 pixel per thread
// ============================================================
extern "C" __global__ void __launch_bounds__(256)
kC(const float* __restrict__ feat)
{
    __shared__ float s_k0nT[C_ * 20];   // [c][k] padded to 20 for float4 loads
    const int tid = threadIdx.x;
    for (int idx = tid; idx < KC; idx += 256) {
        const int k = idx >> 8;
        const int c = idx & 255;
        s_k0nT[c * 20 + k] = g_k0n[idx];
    }
    for (int c = tid; c < C_; c += 256) s_k0nT[c * 20 + 19] = 0.f;
    __syncthreads();

    const int p  = blockIdx.x * 256 + tid;
    const int b  = p >> 16;
    const int hw = p & 65535;
    const float* fp = feat + (size_t)b * C_ * HW + hw;

    float s[K_];
#pragma unroll
    for (int k = 0; k < K_; k++) s[k] = 0.f;

#pragma unroll 4
    for (int c = 0; c < C_; c++) {
        const float v = __ldg(fp + (size_t)c * HW);
        const float4* row = (const float4*)(s_k0nT + c * 20);
        const float4 w0 = row[0], w1 = row[1], w2 = row[2], w3 = row[3], w4 = row[4];
        s[0]  = fmaf(w0.x, v, s[0]);  s[1]  = fmaf(w0.y, v, s[1]);
        s[2]  = fmaf(w0.z, v, s[2]);  s[3]  = fmaf(w0.w, v, s[3]);
        s[4]  = fmaf(w1.x, v, s[4]);  s[5]  = fmaf(w1.y, v, s[5]);
        s[6]  = fmaf(w1.z, v, s[6]);  s[7]  = fmaf(w1.w, v, s[7]);
        s[8]  = fmaf(w2.x, v, s[8]);  s[9]  = fmaf(w2.y, v, s[9]);
        s[10] = fmaf(w2.z, v, s[10]); s[11] = fmaf(w2.w, v, s[11]);
        s[12] = fmaf(w3.x, v, s[12]); s[13] = fmaf(w3.y, v, s[13]);
        s[14] = fmaf(w3.z, v, s[14]); s[15] = fmaf(w3.w, v, s[15]);
        s[16] = fmaf(w4.x, v, s[16]); s[17] = fmaf(w4.y, v, s[17]);
        s[18] = fmaf(w4.z, v, s[18]);
    }

    const float2 npr = g_npr[p];
    const float rnt = npr.y * (1.0f / TAU);
    float mx = -3.4e38f;
#pragma unroll
    for (int k = 0; k < K_; k++) {
        s[k] *= rnt;
        mx = fmaxf(mx, s[k]);
    }
    float sum = 0.f;
#pragma unroll
    for (int k = 0; k < K_; k++) sum += __expf(s[k] - mx);
    const float lse = mx + __logf(sum);

    const float contrib = npr.x * lse;

    __shared__ float red[256];
    red[tid] = contrib;
    __syncthreads();
    for (int st = 128; st > 0; st >>= 1) {
        if (tid < st) red[tid] += red[tid + st];
        __syncthreads();
    }
    if (tid == 0) g_lsepart[blockIdx.x] = red[0];
}

// ============================================================
// Kernel D: final scalar loss
// ============================================================
extern "C" __global__ void kD(float* __restrict__ out)
{
    __shared__ float red[256];
    __shared__ int   redi[256];
    const int tid = threadIdx.x;

    float a = 0.f;
    for (int i = tid; i < NBLK_C; i += 256) a += g_lsepart[i];
    float nk = 0.f;
    if (tid < K_) nk = g_normk[tid];
    int np = 0;
    for (int i = tid; i < NBLK_A; i += 256) np += g_nposblk[i];

    red[tid]  = a - nk * (1.0f / TAU);
    redi[tid] = np;
    __syncthreads();
    for (int s = 128; s > 0; s >>= 1) {
        if (tid < s) { red[tid] += red[tid + s]; redi[tid] += redi[tid + s]; }
        __syncthreads();
    }
    if (tid == 0) out[0] = red[0] / (float)redi[0];
}

// ============================================================
// launch
// ============================================================
extern "C" void kernel_launch(void* const* d_in, const int* in_sizes, int n_in,
                              void* d_out, int out_size)
{
    const float* feat = (const float*)d_in[0];
    const float* gt   = (const float*)d_in[1];
    float* out        = (float*)d_out;

    const int smemA = (2 * C_ * TSTRIDE + K_ * TILE_Q + 256 + K_ * TILE_Q)
                      * (int)sizeof(float);                      // 150016 B
    cudaFuncSetAttribute(kA, cudaFuncAttributeMaxDynamicSharedMemorySize, smemA);

    kA<<<NBLK_A, 256, smemA>>>(feat, gt);
    kB<<<K_, 256>>>();
    kC<<<NBLK_C, 256>>>(feat);
    kD<<<1, 256>>>(out);
}

// round 8
// speedup vs baseline: 2.4913x; 1.8100x over previous
#include <cuda_runtime.h>
#include <math.h>

#define TAU 0.07f
#define EPSN 1e-12f

constexpr int B_   = 4;
constexpr int C_   = 256;
constexpr int K_   = 19;
constexpr int HW   = 65536;          // 256*256
constexpr int P    = B_ * HW;        // 262144
constexpr int TILE_Q = 64;           // kA pixels per tile
constexpr int NTILES = P / TILE_Q;   // 4096
constexpr int NBLK   = 148;          // persistent CTAs (1/SM)
constexpr int KC     = K_ * C_;      // 4864
constexpr int TSA    = 68;           // kA tile pixel-stride  (68 % 32 == 4 -> A frag conflict-free)
constexpr int WS     = 40;           // w / k0n class-stride  (40 % 32 == 8 -> B frag conflict-free)
constexpr int PS     = 264;          // kC slab pixel-stride  (264 % 32 == 8 -> A frag conflict-free)
constexpr int CTILE  = 256;          // kC pixels per tile
constexpr int NCTILE = P / CTILE;    // 1024
constexpr int SLABC  = 64;           // kC channels per slab
constexpr int NSLAB  = C_ / SLABC;   // 4

// ---- scratch (static __device__, no allocation) ----
__device__ float  g_part[(size_t)NBLK * KC];
__device__ float2 g_npr[P];          // (npos, rn) per pixel
__device__ float  g_k0n[KC];         // tf32-valued prototypes
__device__ float  g_normk[K_];
__device__ int    g_nposblk[NBLK];
__device__ float  g_lsepart[NBLK];

// ---- PTX helpers ----
__device__ __forceinline__ unsigned smem_u32(const void* p) {
    return (unsigned)__cvta_generic_to_shared(p);
}
__device__ __forceinline__ void cp16(unsigned dst, const void* src) {
    asm volatile("cp.async.cg.shared.global [%0], [%1], 16;\n" :: "r"(dst), "l"(src));
}
__device__ __forceinline__ void cp_commit() { asm volatile("cp.async.commit_group;\n" ::: "memory"); }
template<int N> __device__ __forceinline__ void cp_wait() {
    asm volatile("cp.async.wait_group %0;\n" :: "n"(N) : "memory");
}
__device__ __forceinline__ unsigned f2tf(float v) {
    unsigned r;
    asm("cvt.rna.tf32.f32 %0, %1;" : "=r"(r) : "f"(v));
    return r;
}
// D += A(m16k8,row) * B(k8n8,col), tf32 inputs, f32 accum
__device__ __forceinline__ void mma_tf32(float* d, const unsigned* a, const unsigned* b) {
    asm volatile(
        "mma.sync.aligned.m16n8k8.row.col.f32.tf32.tf32.f32 "
        "{%0,%1,%2,%3}, {%4,%5,%6,%7}, {%8,%9}, {%0,%1,%2,%3};\n"
        : "+f"(d[0]), "+f"(d[1]), "+f"(d[2]), "+f"(d[3])
        : "r"(a[0]), "r"(a[1]), "r"(a[2]), "r"(a[3]), "r"(b[0]), "r"(b[1]));
}

// ============================================================
// Kernel A: k0[c,k] = sum_p feat[c,p] * w[p,k]   (w = pos?rn:0)
//   grid 148 x 256 threads, ~152KB smem, tensor-core mainloop
// ============================================================
extern "C" __global__ void __launch_bounds__(256, 1)
kA(const float* __restrict__ feat, const float* __restrict__ gt)
{
    extern __shared__ float sm[];
    float* buf0 = sm;                        // [256][68]
    float* buf1 = buf0 + C_ * TSA;           // [256][68]
    float* s_wk = buf1 + C_ * TSA;           // [64][40]  tf32 weights (pixel-major)
    float* s_gt = s_wk + 64 * WS;            // [19][64]
    float* s_sq = s_gt + K_ * 64;            // [256]

    const int tid  = threadIdx.x;
    const int blk  = blockIdx.x;
    const int lane = tid & 31;
    const int wrp  = tid >> 5;
    const int g    = lane >> 2;              // mma group id (0..7)
    const int tg   = lane & 3;               // mma thread-in-group (0..3)
    const int qi   = tid & 15;               // staging float4 slot
    const int cr   = tid >> 4;               // staging channel row base
    const int qof  = tid & 63;               // ssq pixel
    const int cgrp = tid >> 6;               // ssq channel group

    // zero weight buffer once (padding classes 19..23 stay 0 forever)
    for (int i = tid; i < 64 * WS; i += 256) s_wk[i] = 0.f;

    float acc[2][3][4];
#pragma unroll
    for (int mt = 0; mt < 2; mt++)
#pragma unroll
        for (int nt = 0; nt < 3; nt++)
#pragma unroll
            for (int r = 0; r < 4; r++) acc[mt][nt][r] = 0.f;
    int np_acc = 0;

    // ---- tile staging (feat + gt) via 16B cp.async ----
    auto issue = [&](int t, float* buf) {
        const int p0  = t * TILE_Q;
        const int b   = p0 >> 16;
        const int hw0 = p0 & 65535;
        const float* fb = feat + (size_t)b * C_ * HW + hw0;
#pragma unroll
        for (int i = 0; i < 16; i++) {
            const int c = cr + 16 * i;
            cp16(smem_u32(buf + c * TSA + qi * 4), fb + (size_t)c * HW + qi * 4);
        }
        const float* gb = gt + (size_t)b * K_ * HW + hw0;
#pragma unroll
        for (int j = 0; j < 2; j++) {
            const int idx = tid + 256 * j;
            if (idx < (K_ * TILE_Q) / 4) {          // 304 float4s
                const int k  = idx >> 4;
                const int qq = (idx & 15) * 4;
                cp16(smem_u32(s_gt + k * 64 + qq), gb + (size_t)k * HW + qq);
            }
        }
        cp_commit();
    };

    auto do_ssq = [&](const float* buf) {
        const float* col = buf + (cgrp * 64) * TSA + qof;
        float a0 = 0.f, a1 = 0.f, a2 = 0.f, a3 = 0.f;
#pragma unroll
        for (int cc = 0; cc < 64; cc += 4) {
            const float v0 = col[(cc + 0) * TSA];
            const float v1 = col[(cc + 1) * TSA];
            const float v2 = col[(cc + 2) * TSA];
            const float v3 = col[(cc + 3) * TSA];
            a0 = fmaf(v0, v0, a0); a1 = fmaf(v1, v1, a1);
            a2 = fmaf(v2, v2, a2); a3 = fmaf(v3, v3, a3);
        }
        s_sq[cgrp * 64 + qof] = (a0 + a1) + (a2 + a3);
    };

    auto do_mask = [&](int t) {
        if (tid < TILE_Q) {
            const int q = tid;
            const float ssq = s_sq[q] + s_sq[64 + q] + s_sq[128 + q] + s_sq[192 + q];
            const float rn  = 1.0f / fmaxf(sqrtf(ssq), EPSN);
            const float rnt = __uint_as_float(f2tf(rn));
            int np = 0;
#pragma unroll
            for (int k = 0; k < K_; k++) {
                const bool pos = (s_gt[k * 64 + q] == 1.0f);
                s_wk[q * WS + k] = pos ? rnt : 0.f;
                np += pos ? 1 : 0;
            }
            g_npr[t * TILE_Q + q] = make_float2((float)np, rn);
            np_acc += np;
        }
    };

    auto compute = [&](const float* cur) {
        const int R = wrp * 32;
#pragma unroll
        for (int q8 = 0; q8 < 8; q8++) {
            const int p0 = q8 * 8;
            unsigned a[2][4];
#pragma unroll
            for (int mt = 0; mt < 2; mt++) {
                const float* base = cur + (R + 16 * mt + g) * TSA + p0 + tg;
                a[mt][0] = f2tf(base[0]);
                a[mt][1] = f2tf(base[8 * TSA]);
                a[mt][2] = f2tf(base[4]);
                a[mt][3] = f2tf(base[8 * TSA + 4]);
            }
#pragma unroll
            for (int nt = 0; nt < 3; nt++) {
                unsigned b[2];
                const float* wb = s_wk + (p0 + tg) * WS + 8 * nt + g;
                b[0] = __float_as_uint(wb[0]);
                b[1] = __float_as_uint(wb[4 * WS]);
                mma_tf32(acc[0][nt], a[0], b);
                mma_tf32(acc[1][nt], a[1], b);
            }
        }
    };

    // ---- prolog ----
    int t = blk;
    issue(t, buf0);
    cp_wait<0>();
    __syncthreads();
    do_ssq(buf0);
    __syncthreads();
    do_mask(t);
    __syncthreads();

    // ---- pipelined main loop ----
    int bsel = 0;
    while (true) {
        const int tn = t + NBLK;
        const bool hn = (tn < NTILES);
        float* cur = bsel ? buf1 : buf0;
        float* nxt = bsel ? buf0 : buf1;

        if (hn) issue(tn, nxt);
        compute(cur);
        if (!hn) break;

        cp_wait<0>();
        __syncthreads();
        do_ssq(nxt);
        __syncthreads();
        do_mask(tn);
        __syncthreads();

        t = tn;
        bsel ^= 1;
    }

    // ---- epilogue: emit per-block partials (deterministic) ----
    const int R = wrp * 32;
#pragma unroll
    for (int mt = 0; mt < 2; mt++)
#pragma unroll
        for (int nt = 0; nt < 3; nt++)
#pragma unroll
            for (int r = 0; r < 4; r++) {
                const int row = R + 16 * mt + g + 8 * (r >> 1);   // channel
                const int col = 8 * nt + 2 * tg + (r & 1);        // class
                if (col < K_)
                    g_part[(size_t)blk * KC + col * C_ + row] = acc[mt][nt][r];
            }

    __syncthreads();
    int* si = (int*)s_sq;
    if (tid < TILE_Q) si[tid] = np_acc;
    __syncthreads();
    if (tid == 0) {
        int s = 0;
        for (int i = 0; i < TILE_Q; i++) s += si[i];
        g_nposblk[blk] = s;
    }
}

// ============================================================
// Kernel B: reduce k0 partials -> k0n (tf32-valued), norms
// ============================================================
extern "C" __global__ void kB()
{
    const int k = blockIdx.x;
    const int c = threadIdx.x;
    float v = 0.f;
#pragma unroll 4
    for (int b = 0; b < NBLK; b++)
        v += g_part[(size_t)b * KC + k * C_ + c];

    __shared__ float red[256];
    red[c] = v * v;
    __syncthreads();
    for (int s = 128; s > 0; s >>= 1) {
        if (c < s) red[c] += red[c + s];
        __syncthreads();
    }
    const float ssq = red[0];
    const float inv = 1.0f / fmaxf(sqrtf(ssq), EPSN);
    g_k0n[k * C_ + c] = __uint_as_float(f2tf(v * inv));  // pre-converted to tf32
    if (c == 0) g_normk[k] = ssq * inv;                  // = k0n . k0 (exact fp32)
}

// ============================================================
// Kernel C: logits via tensor cores + lse, persistent CTAs
//   tile = 256 pixels, slabs of 64 channels double-buffered
// ============================================================
extern "C" __global__ void __launch_bounds__(256, 1)
kC(const float* __restrict__ feat)
{
    extern __shared__ float sm[];
    float* slab0 = sm;                       // [64][264]
    float* slab1 = slab0 + SLABC * PS;       // [64][264]
    float* s_b   = slab1 + SLABC * PS;       // [256][40] tf32 prototypes (channel-major)
    float* s_red = s_b + C_ * WS;            // [256][26]

    const int tid  = threadIdx.x;
    const int blk  = blockIdx.x;
    const int lane = tid & 31;
    const int wrp  = tid >> 5;
    const int g    = lane >> 2;
    const int tg   = lane & 3;
    const int qi   = tid & 63;               // staging float4 slot (64 per row)
    const int cr   = tid >> 6;               // staging channel row base (0..3)

    // load prototypes (already tf32-valued), zero padding classes
    for (int i = tid; i < C_ * WS; i += 256) s_b[i] = 0.f;
    __syncthreads();
    for (int i = tid; i < KC; i += 256) {
        const int k = i >> 8;
        const int c = i & 255;
        s_b[c * WS + k] = g_k0n[k * C_ + c];
    }
    __syncthreads();

    auto issueSlab = [&](int tile, int s, float* buf) {
        const int p0  = tile * CTILE;
        const int b   = p0 >> 16;
        const int hw0 = p0 & 65535;
        const float* fb = feat + (size_t)b * C_ * HW + hw0 + qi * 4;
        const int c0 = s * SLABC;
#pragma unroll
        for (int i = 0; i < 16; i++) {
            const int cl = cr + 4 * i;
            cp16(smem_u32(buf + cl * PS + qi * 4), fb + (size_t)(c0 + cl) * HW);
        }
        cp_commit();
    };

    float acc[2][3][4];
#pragma unroll
    for (int mt = 0; mt < 2; mt++)
#pragma unroll
        for (int nt = 0; nt < 3; nt++)
#pragma unroll
            for (int r = 0; r < 4; r++) acc[mt][nt][r] = 0.f;
    float lacc = 0.f;

    const int Rp = wrp * 32;

    int tile = blk;
    int bsel = 0;
    if (tile < NCTILE) issueSlab(tile, 0, slab0);

    while (tile < NCTILE) {
        for (int s = 0; s < NSLAB; s++) {
            const int  ntile = (s == NSLAB - 1) ? tile + NBLK : tile;
            const int  ns    = (s + 1) & (NSLAB - 1);
            const bool hn    = (ntile < NCTILE);
            float* cur = bsel ? slab1 : slab0;
            float* nxt = bsel ? slab0 : slab1;

            __syncthreads();                  // prior compute on nxt finished everywhere
            if (hn) { issueSlab(ntile, ns, nxt); cp_wait<1>(); }
            else    { cp_wait<0>(); }
            __syncthreads();

            // ---- mma over this slab's 8 k-chunks ----
#pragma unroll
            for (int q8 = 0; q8 < 8; q8++) {
                const int cl0 = q8 * 8;               // local channel base
                const int ca  = s * SLABC + cl0;      // absolute channel base
                unsigned a[2][4];
#pragma unroll
                for (int mt = 0; mt < 2; mt++) {
                    const float* base = cur + (cl0 + tg) * PS + Rp + 16 * mt + g;
                    a[mt][0] = f2tf(base[0]);
                    a[mt][1] = f2tf(base[8]);
                    a[mt][2] = f2tf(base[4 * PS]);
                    a[mt][3] = f2tf(base[4 * PS + 8]);
                }
#pragma unroll
                for (int nt = 0; nt < 3; nt++) {
                    unsigned b[2];
                    const float* bb = s_b + (ca + tg) * WS + 8 * nt + g;
                    b[0] = __float_as_uint(bb[0]);
                    b[1] = __float_as_uint(bb[4 * WS]);
                    mma_tf32(acc[0][nt], a[0], b);
                    mma_tf32(acc[1][nt], a[1], b);
                }
            }
            bsel ^= 1;
        }

        // ---- epilogue: lse for this tile's 256 pixels (warp-private) ----
#pragma unroll
        for (int mt = 0; mt < 2; mt++)
#pragma unroll
            for (int nt = 0; nt < 3; nt++)
#pragma unroll
                for (int r = 0; r < 4; r++) {
                    const int px  = Rp + 16 * mt + g + 8 * (r >> 1);
                    const int col = 8 * nt + 2 * tg + (r & 1);
                    s_red[px * 26 + col] = acc[mt][nt][r];
                    acc[mt][nt][r] = 0.f;
                }
        __syncwarp();
        {
            const int pxl = Rp + lane;
            const float2 npr = g_npr[tile * CTILE + pxl];
            const float sc = npr.y * (1.0f / TAU);
            const float* rr = s_red + pxl * 26;
            float sum = 0.f;
#pragma unroll
            for (int k = 0; k < K_; k++) sum += __expf(rr[k] * sc);
            lacc += npr.x * __logf(sum);    // |logit| <= ~14.3: no max-shift needed
        }
        __syncwarp();

        tile += NBLK;
    }

    // block-reduce lacc
    __syncthreads();
    s_red[tid] = lacc;
    __syncthreads();
    for (int st = 128; st > 0; st >>= 1) {
        if (tid < st) s_red[tid] += s_red[tid + st];
        __syncthreads();
    }
    if (tid == 0) g_lsepart[blk] = s_red[0];
}

// ============================================================
// Kernel D: final scalar loss
// ============================================================
extern "C" __global__ void kD(float* __restrict__ out)
{
    __shared__ float red[256];
    __shared__ int   redi[256];
    const int tid = threadIdx.x;

    float a = 0.f;
    if (tid < NBLK) a = g_lsepart[tid];
    float nk = 0.f;
    if (tid < K_) nk = g_normk[tid];
    int np = 0;
    if (tid < NBLK) np = g_nposblk[tid];

    red[tid]  = a - nk * (1.0f / TAU);
    redi[tid] = np;
    __syncthreads();
    for (int s = 128; s > 0; s >>= 1) {
        if (tid < s) { red[tid] += red[tid + s]; redi[tid] += redi[tid + s]; }
        __syncthreads();
    }
    if (tid == 0) out[0] = red[0] / (float)redi[0];
}

// ============================================================
// launch
// ============================================================
extern "C" void kernel_launch(void* const* d_in, const int* in_sizes, int n_in,
                              void* d_out, int out_size)
{
    const float* feat = (const float*)d_in[0];
    const float* gt   = (const float*)d_in[1];
    float* out        = (float*)d_out;

    const int smemA = (2 * C_ * TSA + 64 * WS + K_ * 64 + 256) * (int)sizeof(float);   // 155392
    const int smemC = (2 * SLABC * PS + C_ * WS + 256 * 26) * (int)sizeof(float);      // 202752
    cudaFuncSetAttribute(kA, cudaFuncAttributeMaxDynamicSharedMemorySize, smemA);
    cudaFuncSetAttribute(kC, cudaFuncAttributeMaxDynamicSharedMemorySize, smemC);

    kA<<<NBLK, 256, smemA>>>(feat, gt);
    kB<<<K_, 256>>>();
    kC<<<NBLK, 256, smemC>>>(feat);
    kD<<<1, 256>>>(out);
}

// round 9
// speedup vs baseline: 2.5836x; 1.0370x over previous
#include <cuda_runtime.h>
#include <cuda_fp16.h>
#include <math.h>

#define TAU 0.07f
#define EPSN 1e-12f

constexpr int B_   = 4;
constexpr int C_   = 256;
constexpr int K_   = 19;
constexpr int HW   = 65536;          // 256*256
constexpr int P    = B_ * HW;        // 262144
constexpr int TILE_Q = 64;           // kA pixels per tile
constexpr int NTILES = P / TILE_Q;   // 4096
constexpr int NBLK   = 148;          // persistent CTAs (1/SM)
constexpr int KC     = K_ * C_;      // 4864
constexpr int TSA    = 72;           // kA tile pixel-stride (72%32==8 -> LDS.64 A frag conflict-free)
constexpr int WS     = 40;           // class stride in half2/unsigned units (40%32==8)
constexpr int PS     = 260;          // kC slab pixel-stride (260%32==4 -> 2tg*PS+g conflict-free)
constexpr int CTILE  = 256;          // kC pixels per tile
constexpr int NCTILE = P / CTILE;    // 1024
constexpr int SLABC  = 64;           // kC channels per slab
constexpr int NSLAB  = C_ / SLABC;   // 4

// ---- scratch (static __device__, no allocation) ----
__device__ float  g_part[(size_t)NBLK * KC];
__device__ float2 g_npr[P];          // (npos, rn) per pixel (exact f32)
__device__ float  g_k0n[KC];         // exact f32 prototypes
__device__ float  g_normk[K_];
__device__ int    g_nposblk[NBLK];
__device__ float  g_lsepart[NBLK];

// ---- PTX helpers ----
__device__ __forceinline__ unsigned smem_u32(const void* p) {
    return (unsigned)__cvta_generic_to_shared(p);
}
__device__ __forceinline__ void cp16(unsigned dst, const void* src) {
    asm volatile("cp.async.cg.shared.global [%0], [%1], 16;\n" :: "r"(dst), "l"(src));
}
__device__ __forceinline__ void cp_commit() { asm volatile("cp.async.commit_group;\n" ::: "memory"); }
template<int N> __device__ __forceinline__ void cp_wait() {
    asm volatile("cp.async.wait_group %0;\n" :: "n"(N) : "memory");
}
// pack two f32 into f16x2: lo = first arg, hi = second arg
__device__ __forceinline__ unsigned pack_h2(float lo, float hi) {
    unsigned r;
    asm("cvt.rn.f16x2.f32 %0, %1, %2;" : "=r"(r) : "f"(hi), "f"(lo));
    return r;
}
// D += A(m16k16,row) * B(k16n8,col), f16 inputs, f32 accum
__device__ __forceinline__ void mma_f16(float* d, const unsigned* a, const unsigned* b) {
    asm volatile(
        "mma.sync.aligned.m16n8k16.row.col.f32.f16.f16.f32 "
        "{%0,%1,%2,%3}, {%4,%5,%6,%7}, {%8,%9}, {%0,%1,%2,%3};\n"
        : "+f"(d[0]), "+f"(d[1]), "+f"(d[2]), "+f"(d[3])
        : "r"(a[0]), "r"(a[1]), "r"(a[2]), "r"(a[3]), "r"(b[0]), "r"(b[1]));
}

// ============================================================
// Kernel A: k0[c,k] = sum_p feat[c,p] * w[p,k]   (w = pos?rn:0)
//   grid 148 x 256 threads, ~155KB smem, fp16 tensor mainloop
// ============================================================
extern "C" __global__ void __launch_bounds__(256, 1)
kA(const float* __restrict__ feat, const float* __restrict__ gt)
{
    extern __shared__ float sm[];
    float*    buf0  = sm;                        // [256][72] f32
    float*    buf1  = buf0 + C_ * TSA;           // [256][72]
    unsigned* s_wkh = (unsigned*)(buf1 + C_ * TSA);  // [32 pixel-pairs][40] half2
    float*    s_gt  = (float*)(s_wkh + 32 * WS); // [19][64]
    float*    s_sq  = s_gt + K_ * 64;            // [256]

    const int tid  = threadIdx.x;
    const int blk  = blockIdx.x;
    const int lane = tid & 31;
    const int wrp  = tid >> 5;
    const int g    = lane >> 2;              // mma group id (0..7)
    const int tg   = lane & 3;               // mma thread-in-group (0..3)
    const int qi   = tid & 15;               // staging float4 slot
    const int cr   = tid >> 4;               // staging channel row base
    const int qof  = tid & 63;               // ssq pixel
    const int cgrp = tid >> 6;               // ssq channel group

    // zero weight buffer once (padding classes 19..39 stay 0 forever)
    for (int i = tid; i < 32 * WS; i += 256) s_wkh[i] = 0u;

    float acc[2][3][4];
#pragma unroll
    for (int mt = 0; mt < 2; mt++)
#pragma unroll
        for (int nt = 0; nt < 3; nt++)
#pragma unroll
            for (int r = 0; r < 4; r++) acc[mt][nt][r] = 0.f;
    int np_acc = 0;

    auto issue = [&](int t, float* buf) {
        const int p0  = t * TILE_Q;
        const int b   = p0 >> 16;
        const int hw0 = p0 & 65535;
        const float* fb = feat + (size_t)b * C_ * HW + hw0;
#pragma unroll
        for (int i = 0; i < 16; i++) {
            const int c = cr + 16 * i;
            cp16(smem_u32(buf + c * TSA + qi * 4), fb + (size_t)c * HW + qi * 4);
        }
        const float* gb = gt + (size_t)b * K_ * HW + hw0;
#pragma unroll
        for (int j = 0; j < 2; j++) {
            const int idx = tid + 256 * j;
            if (idx < (K_ * TILE_Q) / 4) {          // 304 float4s
                const int k  = idx >> 4;
                const int qq = (idx & 15) * 4;
                cp16(smem_u32(s_gt + k * 64 + qq), gb + (size_t)k * HW + qq);
            }
        }
        cp_commit();
    };

    auto do_ssq = [&](const float* buf) {
        const float* col = buf + (cgrp * 64) * TSA + qof;
        float a0 = 0.f, a1 = 0.f, a2 = 0.f, a3 = 0.f;
#pragma unroll
        for (int cc = 0; cc < 64; cc += 4) {
            const float v0 = col[(cc + 0) * TSA];
            const float v1 = col[(cc + 1) * TSA];
            const float v2 = col[(cc + 2) * TSA];
            const float v3 = col[(cc + 3) * TSA];
            a0 = fmaf(v0, v0, a0); a1 = fmaf(v1, v1, a1);
            a2 = fmaf(v2, v2, a2); a3 = fmaf(v3, v3, a3);
        }
        s_sq[cgrp * 64 + qof] = (a0 + a1) + (a2 + a3);
    };

    auto do_mask = [&](int t) {
        if (tid < TILE_Q) {
            const int q = tid;
            const float ssq = s_sq[q] + s_sq[64 + q] + s_sq[128 + q] + s_sq[192 + q];
            const float rn  = 1.0f / fmaxf(sqrtf(ssq), EPSN);
            const __half rnh  = __float2half_rn(rn);
            const __half zero = __float2half_rn(0.f);
            __half* wh = (__half*)s_wkh;
            const int base = ((q >> 1) * WS) * 2 + (q & 1);
            int np = 0;
#pragma unroll
            for (int k = 0; k < K_; k++) {
                const bool pos = (s_gt[k * 64 + q] == 1.0f);
                wh[base + 2 * k] = pos ? rnh : zero;
                np += pos ? 1 : 0;
            }
            g_npr[t * TILE_Q + q] = make_float2((float)np, rn);
            np_acc += np;
        }
    };

    auto compute = [&](const float* cur) {
        const int R = wrp * 32;
#pragma unroll
        for (int q16 = 0; q16 < 4; q16++) {
            const int p0 = q16 * 16;
            unsigned a[2][4];
#pragma unroll
            for (int mt = 0; mt < 2; mt++) {
                const float* base = cur + (R + 16 * mt + g) * TSA + p0 + 2 * tg;
                const float2 u0 = *(const float2*)(base);
                const float2 u1 = *(const float2*)(base + 8 * TSA);
                const float2 u2 = *(const float2*)(base + 8);
                const float2 u3 = *(const float2*)(base + 8 * TSA + 8);
                a[mt][0] = pack_h2(u0.x, u0.y);
                a[mt][1] = pack_h2(u1.x, u1.y);
                a[mt][2] = pack_h2(u2.x, u2.y);
                a[mt][3] = pack_h2(u3.x, u3.y);
            }
#pragma unroll
            for (int nt = 0; nt < 3; nt++) {
                unsigned b[2];
                b[0] = s_wkh[(p0 / 2 + tg) * WS + 8 * nt + g];
                b[1] = s_wkh[(p0 / 2 + tg + 4) * WS + 8 * nt + g];
                mma_f16(acc[0][nt], a[0], b);
                mma_f16(acc[1][nt], a[1], b);
            }
        }
    };

    // ---- prolog ----
    int t = blk;
    issue(t, buf0);
    cp_wait<0>();
    __syncthreads();
    do_ssq(buf0);
    __syncthreads();
    do_mask(t);
    __syncthreads();

    // ---- pipelined main loop ----
    int bsel = 0;
    while (true) {
        const int tn = t + NBLK;
        const bool hn = (tn < NTILES);
        float* cur = bsel ? buf1 : buf0;
        float* nxt = bsel ? buf0 : buf1;

        if (hn) issue(tn, nxt);
        compute(cur);
        if (!hn) break;

        cp_wait<0>();
        __syncthreads();
        do_ssq(nxt);
        __syncthreads();
        do_mask(tn);
        __syncthreads();

        t = tn;
        bsel ^= 1;
    }

    // ---- epilogue: emit per-block partials (deterministic) ----
    const int R = wrp * 32;
#pragma unroll
    for (int mt = 0; mt < 2; mt++)
#pragma unroll
        for (int nt = 0; nt < 3; nt++)
#pragma unroll
            for (int r = 0; r < 4; r++) {
                const int row = R + 16 * mt + g + 8 * (r >> 1);   // channel
                const int col = 8 * nt + 2 * tg + (r & 1);        // class
                if (col < K_)
                    g_part[(size_t)blk * KC + col * C_ + row] = acc[mt][nt][r];
            }

    __syncthreads();
    int* si = (int*)s_sq;
    if (tid < TILE_Q) si[tid] = np_acc;
    __syncthreads();
    if (tid == 0) {
        int s = 0;
        for (int i = 0; i < TILE_Q; i++) s += si[i];
        g_nposblk[blk] = s;
    }
}

// ============================================================
// Kernel B: reduce k0 partials -> k0n (exact f32), norms
// ============================================================
extern "C" __global__ void kB()
{
    const int k = blockIdx.x;
    const int c = threadIdx.x;
    float v = 0.f;
#pragma unroll 4
    for (int b = 0; b < NBLK; b++)
        v += g_part[(size_t)b * KC + k * C_ + c];

    __shared__ float red[256];
    red[c] = v * v;
    __syncthreads();
    for (int s = 128; s > 0; s >>= 1) {
        if (c < s) red[c] += red[c + s];
        __syncthreads();
    }
    const float ssq = red[0];
    const float inv = 1.0f / fmaxf(sqrtf(ssq), EPSN);
    g_k0n[k * C_ + c] = v * inv;
    if (c == 0) g_normk[k] = ssq * inv;   // = k0n . k0 (exact fp32)
}

// ============================================================
// Kernel C: logits via fp16 tensor cores + lse, persistent CTAs
//   tile = 256 pixels, slabs of 64 channels double-buffered
// ============================================================
extern "C" __global__ void __launch_bounds__(256, 1)
kC(const float* __restrict__ feat)
{
    extern __shared__ float sm[];
    float*    slab0 = sm;                        // [64][260] f32
    float*    slab1 = slab0 + SLABC * PS;        // [64][260]
    unsigned* s_bh  = (unsigned*)(slab1 + SLABC * PS);  // [128 ch-pairs][40] half2
    float*    s_red = (float*)(s_bh + 128 * WS); // [256][26]

    const int tid  = threadIdx.x;
    const int blk  = blockIdx.x;
    const int lane = tid & 31;
    const int wrp  = tid >> 5;
    const int g    = lane >> 2;
    const int tg   = lane & 3;
    const int qi   = tid & 63;               // staging float4 slot (64 per row)
    const int cr   = tid >> 6;               // staging channel row base (0..3)

    // pack prototypes into half2 channel-pairs, zero padding classes
    for (int i = tid; i < 128 * WS; i += 256) s_bh[i] = 0u;
    __syncthreads();
    for (int idx = tid; idx < 128 * K_; idx += 256) {
        const int cp = idx / K_;
        const int k  = idx - cp * K_;
        s_bh[cp * WS + k] = pack_h2(g_k0n[k * C_ + 2 * cp],
                                    g_k0n[k * C_ + 2 * cp + 1]);
    }
    __syncthreads();

    auto issueSlab = [&](int tile, int s, float* buf) {
        const int p0  = tile * CTILE;
        const int b   = p0 >> 16;
        const int hw0 = p0 & 65535;
        const float* fb = feat + (size_t)b * C_ * HW + hw0 + qi * 4;
        const int c0 = s * SLABC;
#pragma unroll
        for (int i = 0; i < 16; i++) {
            const int cl = cr + 4 * i;
            cp16(smem_u32(buf + cl * PS + qi * 4), fb + (size_t)(c0 + cl) * HW);
        }
        cp_commit();
    };

    float acc[2][3][4];
#pragma unroll
    for (int mt = 0; mt < 2; mt++)
#pragma unroll
        for (int nt = 0; nt < 3; nt++)
#pragma unroll
            for (int r = 0; r < 4; r++) acc[mt][nt][r] = 0.f;
    float lacc = 0.f;

    const int Rp = wrp * 32;

    int tile = blk;
    int bsel = 0;
    if (tile < NCTILE) issueSlab(tile, 0, slab0);

    while (tile < NCTILE) {
        for (int s = 0; s < NSLAB; s++) {
            const int  ntile = (s == NSLAB - 1) ? tile + NBLK : tile;
            const int  ns    = (s + 1) & (NSLAB - 1);
            const bool hn    = (ntile < NCTILE);
            float* cur = bsel ? slab1 : slab0;
            float* nxt = bsel ? slab0 : slab1;

            __syncthreads();                  // prior compute on nxt finished everywhere
            if (hn) { issueSlab(ntile, ns, nxt); cp_wait<1>(); }
            else    { cp_wait<0>(); }
            __syncthreads();

            // ---- fp16 mma over this slab's 4 k16 chunks ----
#pragma unroll
            for (int q16 = 0; q16 < 4; q16++) {
                const int cl0 = q16 * 16;             // local channel base
                const int ca  = s * SLABC + cl0;      // absolute channel base
                unsigned a[2][4];
#pragma unroll
                for (int mt = 0; mt < 2; mt++) {
                    const float* base = cur + (cl0 + 2 * tg) * PS + Rp + 16 * mt + g;
                    a[mt][0] = pack_h2(base[0],          base[PS]);
                    a[mt][1] = pack_h2(base[8],          base[PS + 8]);
                    a[mt][2] = pack_h2(base[8 * PS],     base[9 * PS]);
                    a[mt][3] = pack_h2(base[8 * PS + 8], base[9 * PS + 8]);
                }
#pragma unroll
                for (int nt = 0; nt < 3; nt++) {
                    unsigned b[2];
                    b[0] = s_bh[(ca / 2 + tg) * WS + 8 * nt + g];
                    b[1] = s_bh[(ca / 2 + tg + 4) * WS + 8 * nt + g];
                    mma_f16(acc[0][nt], a[0], b);
                    mma_f16(acc[1][nt], a[1], b);
                }
            }
            bsel ^= 1;
        }

        // ---- epilogue: lse for this tile's 256 pixels (warp-private) ----
#pragma unroll
        for (int mt = 0; mt < 2; mt++)
#pragma unroll
            for (int nt = 0; nt < 3; nt++)
#pragma unroll
                for (int r = 0; r < 4; r++) {
                    const int px  = Rp + 16 * mt + g + 8 * (r >> 1);
                    const int col = 8 * nt + 2 * tg + (r & 1);
                    s_red[px * 26 + col] = acc[mt][nt][r];
                    acc[mt][nt][r] = 0.f;
                }
        __syncwarp();
        {
            const int pxl = Rp + lane;
            const float2 npr = g_npr[tile * CTILE + pxl];
            const float sc = npr.y * (1.0f / TAU);
            const float* rr = s_red + pxl * 26;
            float sum = 0.f;
#pragma unroll
            for (int k = 0; k < K_; k++) sum += __expf(rr[k] * sc);
            lacc += npr.x * __logf(sum);    // |logit| <= ~14.3: no max-shift needed
        }
        __syncwarp();

        tile += NBLK;
    }

    // block-reduce lacc
    __syncthreads();
    s_red[tid] = lacc;
    __syncthreads();
    for (int st = 128; st > 0; st >>= 1) {
        if (tid < st) s_red[tid] += s_red[tid + st];
        __syncthreads();
    }
    if (tid == 0) g_lsepart[blk] = s_red[0];
}

// ============================================================
// Kernel D: final scalar loss
// ============================================================
extern "C" __global__ void kD(float* __restrict__ out)
{
    __shared__ float red[256];
    __shared__ int   redi[256];
    const int tid = threadIdx.x;

    float a = 0.f;
    if (tid < NBLK) a = g_lsepart[tid];
    float nk = 0.f;
    if (tid < K_) nk = g_normk[tid];
    int np = 0;
    if (tid < NBLK) np = g_nposblk[tid];

    red[tid]  = a - nk * (1.0f / TAU);
    redi[tid] = np;
    __syncthreads();
    for (int s = 128; s > 0; s >>= 1) {
        if (tid < s) { red[tid] += red[tid + s]; redi[tid] += redi[tid + s]; }
        __syncthreads();
    }
    if (tid == 0) out[0] = red[0] / (float)redi[0];
}

// ============================================================
// launch
// ============================================================
extern "C" void kernel_launch(void* const* d_in, const int* in_sizes, int n_in,
                              void* d_out, int out_size)
{
    const float* feat = (const float*)d_in[0];
    const float* gt   = (const float*)d_in[1];
    float* out        = (float*)d_out;

    const int smemA = (2 * C_ * TSA + 32 * WS + K_ * 64 + 256) * (int)sizeof(float);   // 158464
    const int smemC = (2 * SLABC * PS + 128 * WS + 256 * 26) * (int)sizeof(float);     // 180224
    cudaFuncSetAttribute(kA, cudaFuncAttributeMaxDynamicSharedMemorySize, smemA);
    cudaFuncSetAttribute(kC, cudaFuncAttributeMaxDynamicSharedMemorySize, smemC);

    kA<<<NBLK, 256, smemA>>>(feat, gt);
    kB<<<K_, 256>>>();
    kC<<<NBLK, 256, smemC>>>(feat);
    kD<<<1, 256>>>(out);
}

// round 10
// speedup vs baseline: 2.8473x; 1.1021x over previous
#include <cuda_runtime.h>
#include <cuda_fp16.h>
#include <math.h>

#define TAU 0.07f
#define EPSN 1e-12f

constexpr int B_   = 4;
constexpr int C_   = 256;
constexpr int K_   = 19;
constexpr int HW   = 65536;          // 256*256
constexpr int P    = B_ * HW;        // 262144
constexpr int NBLK = 148;            // persistent CTAs (1/SM)
constexpr int KC   = K_ * C_;        // 4864
// kA
constexpr int TQ   = 32;             // pixels per kA tile
constexpr int NTA  = P / TQ;         // 8192 tiles
constexpr int TSA  = 40;             // tile pixel-stride (40%32==8 -> LDS.64 conflict-free)
// kC
constexpr int PS    = 260;           // slab pixel-stride (260%32==4 -> 8tg+g conflict-free)
constexpr int CTILE = 256;           // pixels per kC tile
constexpr int NCT   = P / CTILE;     // 1024
constexpr int SLABC = 32;            // channels per chunk
constexpr int WS    = 40;            // class stride (half2 units)

// ---- scratch (static __device__, no allocation) ----
__device__ float  g_part[(size_t)NBLK * KC];
__device__ float2 g_npr[P];          // (npos, rn) per pixel
__device__ float  g_k0n[KC];
__device__ float  g_normk[K_];
__device__ int    g_nposblk[NBLK];
__device__ float  g_lsepart[NBLK];

// ---- PTX helpers ----
__device__ __forceinline__ unsigned smem_u32(const void* p) {
    return (unsigned)__cvta_generic_to_shared(p);
}
__device__ __forceinline__ void cp16(unsigned dst, const void* src) {
    asm volatile("cp.async.cg.shared.global [%0], [%1], 16;\n" :: "r"(dst), "l"(src));
}
__device__ __forceinline__ void cp_commit() { asm volatile("cp.async.commit_group;\n" ::: "memory"); }
template<int N> __device__ __forceinline__ void cp_wait() {
    asm volatile("cp.async.wait_group %0;\n" :: "n"(N) : "memory");
}
__device__ __forceinline__ unsigned pack_h2(float lo, float hi) {
    unsigned r;
    asm("cvt.rn.f16x2.f32 %0, %1, %2;" : "=r"(r) : "f"(hi), "f"(lo));
    return r;
}
__device__ __forceinline__ void mma_f16(float* d, const unsigned* a, const unsigned* b) {
    asm volatile(
        "mma.sync.aligned.m16n8k16.row.col.f32.f16.f16.f32 "
        "{%0,%1,%2,%3}, {%4,%5,%6,%7}, {%8,%9}, {%0,%1,%2,%3};\n"
        : "+f"(d[0]), "+f"(d[1]), "+f"(d[2]), "+f"(d[3])
        : "r"(a[0]), "r"(a[1]), "r"(a[2]), "r"(a[3]), "r"(b[0]), "r"(b[1]));
}

// ============================================================
// Kernel A: k0[c,k] = sum_p feat[c,p]*w[p,k], ring-4 pipeline
//   grid 148 x 256 threads, ~185KB smem
// ============================================================
extern "C" __global__ void __launch_bounds__(256, 1)
kA(const float* __restrict__ feat, const float* __restrict__ gt)
{
    extern __shared__ float sm[];
    float*    fbuf = sm;                               // 4 x [256][40]
    unsigned* wk   = (unsigned*)(sm + 4 * C_ * TSA);   // 4 x [16 pairs][40]
    float*    sgt  = (float*)(wk + 4 * 16 * WS);       // 4 x [19][32]
    float*    ssq  = sgt + 4 * K_ * TQ;                // [256]

    const int tid  = threadIdx.x;
    const int blk  = blockIdx.x;
    const int lane = tid & 31;
    const int wrp  = tid >> 5;
    const int g    = lane >> 2;
    const int tg   = lane & 3;
    const int qi   = tid & 7;        // staging float4 slot (8 per 32px row)
    const int cr   = tid >> 3;       // staging channel base (0..31)

    for (int i = tid; i < 4 * 16 * WS; i += 256) wk[i] = 0u;

    float acc[2][3][4];
#pragma unroll
    for (int mt = 0; mt < 2; mt++)
#pragma unroll
        for (int nt = 0; nt < 3; nt++)
#pragma unroll
            for (int r = 0; r < 4; r++) acc[mt][nt][r] = 0.f;
    int np_acc = 0;

    auto issue = [&](int jj) {
        const int t = blk + jj * NBLK;
        if (t < NTA) {
            float* buf = fbuf + (jj & 3) * (C_ * TSA);
            const int p0  = t * TQ;
            const int b   = p0 >> 16;
            const int hw0 = p0 & 65535;
            const float* fb = feat + (size_t)b * C_ * HW + hw0;
#pragma unroll
            for (int i = 0; i < 8; i++) {
                const int c = cr + 32 * i;
                cp16(smem_u32(buf + c * TSA + qi * 4), fb + (size_t)c * HW + qi * 4);
            }
            if (tid < (K_ * TQ) / 4) {   // 152 float4s of gt
                const int k  = tid >> 3;
                const int qq = (tid & 7) * 4;
                cp16(smem_u32(sgt + (jj & 3) * (K_ * TQ) + k * TQ + qq),
                     gt + (size_t)b * K_ * HW + hw0 + (size_t)k * HW + qq);
            }
        }
        cp_commit();
    };

    auto dossq = [&](int jj) {
        const float* col = fbuf + (jj & 3) * (C_ * TSA) + (wrp * 32) * TSA + lane;
        float a0 = 0.f, a1 = 0.f, a2 = 0.f, a3 = 0.f;
#pragma unroll
        for (int cc = 0; cc < 32; cc += 4) {
            const float v0 = col[(cc + 0) * TSA];
            const float v1 = col[(cc + 1) * TSA];
            const float v2 = col[(cc + 2) * TSA];
            const float v3 = col[(cc + 3) * TSA];
            a0 = fmaf(v0, v0, a0); a1 = fmaf(v1, v1, a1);
            a2 = fmaf(v2, v2, a2); a3 = fmaf(v3, v3, a3);
        }
        ssq[wrp * 32 + lane] = (a0 + a1) + (a2 + a3);
    };

    auto domask = [&](int jj, int t) {
        if (tid < TQ) {
            const int q = tid;
            float s = 0.f;
#pragma unroll
            for (int w = 0; w < 8; w++) s += ssq[w * 32 + q];
            const float rn = 1.0f / fmaxf(sqrtf(s), EPSN);
            const __half rnh  = __float2half_rn(rn);
            const __half zero = __float2half_rn(0.f);
            __half* wh = (__half*)(wk + (jj & 3) * (16 * WS));
            const float* gtt = sgt + (jj & 3) * (K_ * TQ);
            const int base = ((q >> 1) * WS) * 2 + (q & 1);
            int np = 0;
#pragma unroll
            for (int k = 0; k < K_; k++) {
                const bool pos = (gtt[k * TQ + q] == 1.0f);
                wh[base + 2 * k] = pos ? rnh : zero;
                np += pos ? 1 : 0;
            }
            g_npr[t * TQ + q] = make_float2((float)np, rn);
            np_acc += np;
        }
    };

    auto compute = [&](int jj) {
        const float*    cur = fbuf + (jj & 3) * (C_ * TSA);
        const unsigned* wks = wk + (jj & 3) * (16 * WS);
        const int R = wrp * 32;
#pragma unroll
        for (int q16 = 0; q16 < 2; q16++) {
            const int p0 = 16 * q16;
            unsigned a[2][4];
#pragma unroll
            for (int mt = 0; mt < 2; mt++) {
                const float* base = cur + (R + 16 * mt + g) * TSA + p0 + 2 * tg;
                const float2 u0 = *(const float2*)(base);
                const float2 u1 = *(const float2*)(base + 8 * TSA);
                const float2 u2 = *(const float2*)(base + 8);
                const float2 u3 = *(const float2*)(base + 8 * TSA + 8);
                a[mt][0] = pack_h2(u0.x, u0.y);
                a[mt][1] = pack_h2(u1.x, u1.y);
                a[mt][2] = pack_h2(u2.x, u2.y);
                a[mt][3] = pack_h2(u3.x, u3.y);
            }
#pragma unroll
            for (int nt = 0; nt < 3; nt++) {
                unsigned b[2];
                b[0] = wks[(p0 / 2 + tg) * WS + 8 * nt + g];
                b[1] = wks[(p0 / 2 + tg + 4) * WS + 8 * nt + g];
                mma_f16(acc[0][nt], a[0], b);
                mma_f16(acc[1][nt], a[1], b);
            }
        }
    };

    // ---- prolog: 3 tiles in flight, pre-mask tile 0 ----
    issue(0); issue(1); issue(2);
    cp_wait<2>();
    __syncthreads();
    dossq(0);
    __syncthreads();
    domask(0, blk);

    // ---- main loop: DRAM kept 3 tiles deep ----
    int j = 0;
    while (blk + j * NBLK < NTA) {
        __syncthreads();                 // wk[j] visible; slot (j-1)&3 free
        issue(j + 3);
        cp_wait<2>();                    // tile j+1 arrived
        __syncthreads();
        const int t1 = blk + (j + 1) * NBLK;
        if (t1 < NTA) dossq(j + 1);
        __syncthreads();
        if (t1 < NTA) domask(j + 1, t1);
        compute(j);                      // reads wk[j&3], buf[j&3] — no conflict with mask(j+1)
        j++;
    }

    // ---- epilogue: per-block partials (deterministic) ----
    const int R = wrp * 32;
#pragma unroll
    for (int mt = 0; mt < 2; mt++)
#pragma unroll
        for (int nt = 0; nt < 3; nt++)
#pragma unroll
            for (int r = 0; r < 4; r++) {
                const int row = R + 16 * mt + g + 8 * (r >> 1);   // channel
                const int col = 8 * nt + 2 * tg + (r & 1);        // class
                if (col < K_)
                    g_part[(size_t)blk * KC + col * C_ + row] = acc[mt][nt][r];
            }

    __syncthreads();
    int* si = (int*)ssq;
    if (tid < TQ) si[tid] = np_acc;
    __syncthreads();
    if (tid == 0) {
        int s = 0;
        for (int i = 0; i < TQ; i++) s += si[i];
        g_nposblk[blk] = s;
    }
}

// ============================================================
// Kernel B: reduce k0 partials -> k0n, norms (1024 thr, 4x MLP)
// ============================================================
extern "C" __global__ void kB()
{
    const int k = blockIdx.x;
    const int tid = threadIdx.x;
    const int c = tid & 255;
    const int s = tid >> 8;              // 0..3
    float v = 0.f;
    const int b0 = s * 37, b1 = b0 + 37; // 4*37 = 148
#pragma unroll 4
    for (int b = b0; b < b1; b++)
        v += g_part[(size_t)b * KC + k * C_ + c];

    __shared__ float red[1024];
    red[tid] = v;
    __syncthreads();
    float w = 0.f;
    if (tid < 256) w = red[c] + red[c + 256] + red[c + 512] + red[c + 768];
    __syncthreads();
    if (tid < 256) red[c] = w * w;
    __syncthreads();
    for (int st = 128; st > 0; st >>= 1) {
        if (tid < st) red[tid] += red[tid + st];
        __syncthreads();
    }
    const float ssq = red[0];
    const float inv = 1.0f / fmaxf(sqrtf(ssq), EPSN);
    if (tid < 256) g_k0n[k * C_ + c] = w * inv;
    if (tid == 0)  g_normk[k] = ssq * inv;   // = k0n . k0
}

// ============================================================
// Kernel C: logits + lse; ring-4 of 32-ch chunks streaming
//   across tile boundaries; register-only shfl epilogue
// ============================================================
extern "C" __global__ void __launch_bounds__(256, 1)
kC(const float* __restrict__ feat)
{
    extern __shared__ float sm[];
    float*    ring = sm;                                 // 4 x [32][260]
    unsigned* sbh  = (unsigned*)(sm + 4 * SLABC * PS);   // [128 ch-pairs][40] half2
    __shared__ float sred[256];

    const int tid  = threadIdx.x;
    const int blk  = blockIdx.x;
    const int lane = tid & 31;
    const int wrp  = tid >> 5;
    const int g    = lane >> 2;
    const int tg   = lane & 3;
    const int qi   = tid & 63;       // staging float4 slot (64 per 256px row)
    const int cr   = tid >> 6;       // staging channel base (0..3)

    // prototypes -> half2 channel-pairs
    for (int i = tid; i < 128 * WS; i += 256) sbh[i] = 0u;
    __syncthreads();
    for (int idx = tid; idx < 128 * K_; idx += 256) {
        const int cp = idx / K_;
        const int k  = idx - cp * K_;
        sbh[cp * WS + k] = pack_h2(g_k0n[k * C_ + 2 * cp],
                                   g_k0n[k * C_ + 2 * cp + 1]);
    }
    __syncthreads();

    auto issue = [&](int m) {
        const int tile = blk + (m >> 3) * NBLK;
        if (tile < NCT) {
            const int s  = m & 7;
            const int c0 = s * SLABC;
            float* buf = ring + (m & 3) * (SLABC * PS);
            const int p0  = tile * CTILE;
            const int b   = p0 >> 16;
            const int hw0 = p0 & 65535;
            const float* fb = feat + (size_t)b * C_ * HW + hw0 + qi * 4;
#pragma unroll
            for (int i = 0; i < 8; i++) {
                const int cl = cr + 4 * i;
                cp16(smem_u32(buf + cl * PS + qi * 4), fb + (size_t)(c0 + cl) * HW);
            }
        }
        cp_commit();
    };

    float acc[2][3][4];
#pragma unroll
    for (int mt = 0; mt < 2; mt++)
#pragma unroll
        for (int nt = 0; nt < 3; nt++)
#pragma unroll
            for (int r = 0; r < 4; r++) acc[mt][nt][r] = 0.f;
    float lacc = 0.f;
    const int Rp = wrp * 32;

    issue(0); issue(1); issue(2);

    int m = 0;
    while (blk + (m >> 3) * NBLK < NCT) {
        __syncthreads();                 // slot (m-1)&3 free
        issue(m + 3);
        cp_wait<2>();                    // chunk m+1 arrived; m long done
        __syncthreads();

        const float* cur = ring + (m & 3) * (SLABC * PS);
        const int s = m & 7;
#pragma unroll
        for (int q16 = 0; q16 < 2; q16++) {
            const int cl0 = 16 * q16;
            unsigned a[2][4];
#pragma unroll
            for (int mt = 0; mt < 2; mt++) {
                const float* base = cur + (cl0 + 2 * tg) * PS + Rp + 16 * mt + g;
                a[mt][0] = pack_h2(base[0],          base[PS]);
                a[mt][1] = pack_h2(base[8],          base[PS + 8]);
                a[mt][2] = pack_h2(base[8 * PS],     base[9 * PS]);
                a[mt][3] = pack_h2(base[8 * PS + 8], base[9 * PS + 8]);
            }
            const int cpi = s * 16 + 8 * q16;
#pragma unroll
            for (int nt = 0; nt < 3; nt++) {
                unsigned b[2];
                b[0] = sbh[(cpi + tg) * WS + 8 * nt + g];
                b[1] = sbh[(cpi + tg + 4) * WS + 8 * nt + g];
                mma_f16(acc[0][nt], a[0], b);
                mma_f16(acc[1][nt], a[1], b);
            }
        }

        if ((s) == 7) {
            // ---- register-only epilogue for this tile's 256 pixels ----
            const int tile = blk + (m >> 3) * NBLK;
            const int pb = tile * CTILE + Rp;
            float2 npr[4];
#pragma unroll
            for (int mt = 0; mt < 2; mt++)
#pragma unroll
                for (int rh = 0; rh < 2; rh++)
                    npr[2 * mt + rh] = g_npr[pb + 16 * mt + g + 8 * rh];

            float sume[4];
#pragma unroll
            for (int mt = 0; mt < 2; mt++)
#pragma unroll
                for (int rh = 0; rh < 2; rh++) {
                    const int i = 2 * mt + rh;
                    const float sc = npr[i].y * (1.0f / TAU);
                    float sum = 0.f;
#pragma unroll
                    for (int nt = 0; nt < 3; nt++)
#pragma unroll
                        for (int rl = 0; rl < 2; rl++) {
                            const int col = 8 * nt + 2 * tg + rl;
                            const float v = acc[mt][nt][2 * rh + rl];
                            sum += (col < K_) ? __expf(v * sc) : 0.f;
                        }
                    sume[i] = sum;
                }
            // quad reduction over tg (lane&3): xor 1, 2 stay inside quad
#pragma unroll
            for (int i = 0; i < 4; i++) {
                sume[i] += __shfl_xor_sync(0xffffffffu, sume[i], 1);
                sume[i] += __shfl_xor_sync(0xffffffffu, sume[i], 2);
            }
            if (tg == 0) {
#pragma unroll
                for (int i = 0; i < 4; i++)
                    lacc += npr[i].x * __logf(sume[i]);   // |logit| <= ~14.3
            }
#pragma unroll
            for (int mt = 0; mt < 2; mt++)
#pragma unroll
                for (int nt = 0; nt < 3; nt++)
#pragma unroll
                    for (int r = 0; r < 4; r++) acc[mt][nt][r] = 0.f;
        }
        m++;
    }

    // block-reduce lacc
    __syncthreads();
    sred[tid] = lacc;
    __syncthreads();
    for (int st = 128; st > 0; st >>= 1) {
        if (tid < st) sred[tid] += sred[tid + st];
        __syncthreads();
    }
    if (tid == 0) g_lsepart[blk] = sred[0];
}

// ============================================================
// Kernel D: final scalar loss
// ============================================================
extern "C" __global__ void kD(float* __restrict__ out)
{
    __shared__ float red[256];
    __shared__ int   redi[256];
    const int tid = threadIdx.x;

    float a = 0.f;
    if (tid < NBLK) a = g_lsepart[tid];
    float nk = 0.f;
    if (tid < K_) nk = g_normk[tid];
    int np = 0;
    if (tid < NBLK) np = g_nposblk[tid];

    red[tid]  = a - nk * (1.0f / TAU);
    redi[tid] = np;
    __syncthreads();
    for (int s = 128; s > 0; s >>= 1) {
        if (tid < s) { red[tid] += red[tid + s]; redi[tid] += redi[tid + s]; }
        __syncthreads();
    }
    if (tid == 0) out[0] = red[0] / (float)redi[0];
}

// ============================================================
// launch
// ============================================================
extern "C" void kernel_launch(void* const* d_in, const int* in_sizes, int n_in,
                              void* d_out, int out_size)
{
    const float* feat = (const float*)d_in[0];
    const float* gt   = (const float*)d_in[1];
    float* out        = (float*)d_out;

    const int smemA = (4 * C_ * TSA) * 4 + (4 * 16 * WS) * 4
                    + (4 * K_ * TQ) * 4 + 256 * 4;          // 184832 B
    const int smemC = (4 * SLABC * PS) * 4 + (128 * WS) * 4; // 153600 B
    cudaFuncSetAttribute(kA, cudaFuncAttributeMaxDynamicSharedMemorySize, smemA);
    cudaFuncSetAttribute(kC, cudaFuncAttributeMaxDynamicSharedMemorySize, smemC);

    kA<<<NBLK, 256, smemA>>>(feat, gt);
    kB<<<K_, 1024>>>();
    kC<<<NBLK, 256, smemC>>>(feat);
    kD<<<1, 256>>>(out);
}

// round 11
// speedup vs baseline: 3.2358x; 1.1365x over previous
#include <cuda_runtime.h>
#include <cuda_fp16.h>
#include <math.h>

#define TAU 0.07f
#define EPSN 1e-12f

constexpr int B_   = 4;
constexpr int C_   = 256;
constexpr int K_   = 19;
constexpr int HW   = 65536;          // 256*256
constexpr int P    = B_ * HW;        // 262144
constexpr int NBLK = 296;            // persistent CTAs (2/SM)
constexpr int KC   = K_ * C_;        // 4864
// kA
constexpr int TQ   = 32;             // pixels per kA tile
constexpr int NTA  = P / TQ;         // 8192 tiles
constexpr int TSA  = 40;             // tile pixel-stride (40%32==8 -> LDS.64 conflict-free)
// kC
constexpr int PS    = 260;           // slab pixel-stride (260%32==4 -> 8tg+g conflict-free)
constexpr int CTILE = 256;           // pixels per kC tile
constexpr int NCT   = P / CTILE;     // 1024
constexpr int SLABC = 16;            // channels per chunk
constexpr int NCH   = C_ / SLABC;    // 16 chunks per tile
constexpr int WS    = 40;            // class stride (half2 units)

// ---- scratch (static __device__, no allocation) ----
__device__ float  g_part[(size_t)NBLK * KC];
__device__ float2 g_npr[P];          // (npos, rn) per pixel
__device__ float  g_k0n[KC];
__device__ float  g_normk[K_];
__device__ int    g_nposblk[NBLK];
__device__ float  g_lsepart[NBLK];

// ---- PTX helpers ----
__device__ __forceinline__ unsigned smem_u32(const void* p) {
    return (unsigned)__cvta_generic_to_shared(p);
}
__device__ __forceinline__ void cp16(unsigned dst, const void* src) {
    asm volatile("cp.async.cg.shared.global [%0], [%1], 16;\n" :: "r"(dst), "l"(src));
}
__device__ __forceinline__ void cp_commit() { asm volatile("cp.async.commit_group;\n" ::: "memory"); }
template<int N> __device__ __forceinline__ void cp_wait() {
    asm volatile("cp.async.wait_group %0;\n" :: "n"(N) : "memory");
}
__device__ __forceinline__ unsigned pack_h2(float lo, float hi) {
    unsigned r;
    asm("cvt.rn.f16x2.f32 %0, %1, %2;" : "=r"(r) : "f"(hi), "f"(lo));
    return r;
}
__device__ __forceinline__ void mma_f16(float* d, const unsigned* a, const unsigned* b) {
    asm volatile(
        "mma.sync.aligned.m16n8k16.row.col.f32.f16.f16.f32 "
        "{%0,%1,%2,%3}, {%4,%5,%6,%7}, {%8,%9}, {%0,%1,%2,%3};\n"
        : "+f"(d[0]), "+f"(d[1]), "+f"(d[2]), "+f"(d[3])
        : "r"(a[0]), "r"(a[1]), "r"(a[2]), "r"(a[3]), "r"(b[0]), "r"(b[1]));
}

// ============================================================
// Kernel A: k0[c,k] = sum_p feat[c,p]*w[p,k]
//   296 CTAs (2/SM), ring-2 of 32-pixel tiles, ~91KB smem
// ============================================================
extern "C" __global__ void __launch_bounds__(256, 2)
kA(const float* __restrict__ feat, const float* __restrict__ gt)
{
    extern __shared__ float sm[];
    float*    fbuf = sm;                               // 2 x [256][40]
    unsigned* wk   = (unsigned*)(sm + 2 * C_ * TSA);   // 2 x [16 pairs][40]
    float*    sgt  = (float*)(wk + 2 * 16 * WS);       // 2 x [19][32]
    float*    ssq  = sgt + 2 * K_ * TQ;                // [256]

    const int tid  = threadIdx.x;
    const int blk  = blockIdx.x;
    const int lane = tid & 31;
    const int wrp  = tid >> 5;
    const int g    = lane >> 2;
    const int tg   = lane & 3;
    const int qi   = tid & 7;        // staging float4 slot (8 per 32px row)
    const int cr   = tid >> 3;       // staging channel base (0..31)

    for (int i = tid; i < 2 * 16 * WS; i += 256) wk[i] = 0u;
    __syncthreads();

    float acc[2][3][4];
#pragma unroll
    for (int mt = 0; mt < 2; mt++)
#pragma unroll
        for (int nt = 0; nt < 3; nt++)
#pragma unroll
            for (int r = 0; r < 4; r++) acc[mt][nt][r] = 0.f;
    int np_acc = 0;

    auto issue = [&](int jj) {
        const int t = blk + jj * NBLK;
        if (t < NTA) {
            float* buf = fbuf + (jj & 1) * (C_ * TSA);
            const int p0  = t * TQ;
            const int b   = p0 >> 16;
            const int hw0 = p0 & 65535;
            const float* fb = feat + (size_t)b * C_ * HW + hw0;
#pragma unroll
            for (int i = 0; i < 8; i++) {
                const int c = cr + 32 * i;
                cp16(smem_u32(buf + c * TSA + qi * 4), fb + (size_t)c * HW + qi * 4);
            }
            if (tid < (K_ * TQ) / 4) {   // 152 float4s of gt
                const int k  = tid >> 3;
                const int qq = (tid & 7) * 4;
                cp16(smem_u32(sgt + (jj & 1) * (K_ * TQ) + k * TQ + qq),
                     gt + (size_t)b * K_ * HW + hw0 + (size_t)k * HW + qq);
            }
        }
        cp_commit();
    };

    auto dossq = [&](int jj) {
        const float* col = fbuf + (jj & 1) * (C_ * TSA) + (wrp * 32) * TSA + lane;
        float a0 = 0.f, a1 = 0.f, a2 = 0.f, a3 = 0.f;
#pragma unroll
        for (int cc = 0; cc < 32; cc += 4) {
            const float v0 = col[(cc + 0) * TSA];
            const float v1 = col[(cc + 1) * TSA];
            const float v2 = col[(cc + 2) * TSA];
            const float v3 = col[(cc + 3) * TSA];
            a0 = fmaf(v0, v0, a0); a1 = fmaf(v1, v1, a1);
            a2 = fmaf(v2, v2, a2); a3 = fmaf(v3, v3, a3);
        }
        ssq[wrp * 32 + lane] = (a0 + a1) + (a2 + a3);
    };

    auto domask = [&](int jj, int t) {
        if (tid < TQ) {
            const int q = tid;
            float s = 0.f;
#pragma unroll
            for (int w = 0; w < 8; w++) s += ssq[w * 32 + q];
            const float rn = 1.0f / fmaxf(sqrtf(s), EPSN);
            const __half rnh  = __float2half_rn(rn);
            const __half zero = __float2half_rn(0.f);
            __half* wh = (__half*)(wk + (jj & 1) * (16 * WS));
            const float* gtt = sgt + (jj & 1) * (K_ * TQ);
            const int base = ((q >> 1) * WS) * 2 + (q & 1);
            int np = 0;
#pragma unroll
            for (int k = 0; k < K_; k++) {
                const bool pos = (gtt[k * TQ + q] == 1.0f);
                wh[base + 2 * k] = pos ? rnh : zero;
                np += pos ? 1 : 0;
            }
            g_npr[t * TQ + q] = make_float2((float)np, rn);
            np_acc += np;
        }
    };

    auto compute = [&](int jj) {
        const float*    cur = fbuf + (jj & 1) * (C_ * TSA);
        const unsigned* wks = wk + (jj & 1) * (16 * WS);
        const int R = wrp * 32;
#pragma unroll
        for (int q16 = 0; q16 < 2; q16++) {
            const int p0 = 16 * q16;
            unsigned a[2][4];
#pragma unroll
            for (int mt = 0; mt < 2; mt++) {
                const float* base = cur + (R + 16 * mt + g) * TSA + p0 + 2 * tg;
                const float2 u0 = *(const float2*)(base);
                const float2 u1 = *(const float2*)(base + 8 * TSA);
                const float2 u2 = *(const float2*)(base + 8);
                const float2 u3 = *(const float2*)(base + 8 * TSA + 8);
                a[mt][0] = pack_h2(u0.x, u0.y);
                a[mt][1] = pack_h2(u1.x, u1.y);
                a[mt][2] = pack_h2(u2.x, u2.y);
                a[mt][3] = pack_h2(u3.x, u3.y);
            }
#pragma unroll
            for (int nt = 0; nt < 3; nt++) {
                unsigned b[2];
                b[0] = wks[(p0 / 2 + tg) * WS + 8 * nt + g];
                b[1] = wks[(p0 / 2 + tg + 4) * WS + 8 * nt + g];
                mma_f16(acc[0][nt], a[0], b);
                mma_f16(acc[1][nt], a[1], b);
            }
        }
    };

    // ---- ring-2 pipeline (sibling CTA on same SM hides stalls) ----
    issue(0); issue(1);
    int j = 0;
    while (blk + j * NBLK < NTA) {
        cp_wait<1>();                 // tile j arrived
        __syncthreads();
        dossq(j);
        __syncthreads();
        domask(j, blk + j * NBLK);
        __syncthreads();
        compute(j);
        __syncthreads();              // slot free
        issue(j + 2);
        j++;
    }

    // ---- epilogue: per-block partials (deterministic) ----
    const int R = wrp * 32;
#pragma unroll
    for (int mt = 0; mt < 2; mt++)
#pragma unroll
        for (int nt = 0; nt < 3; nt++)
#pragma unroll
            for (int r = 0; r < 4; r++) {
                const int row = R + 16 * mt + g + 8 * (r >> 1);   // channel
                const int col = 8 * nt + 2 * tg + (r & 1);        // class
                if (col < K_)
                    g_part[(size_t)blk * KC + col * C_ + row] = acc[mt][nt][r];
            }

    __syncthreads();
    int* si = (int*)ssq;
    if (tid < TQ) si[tid] = np_acc;
    __syncthreads();
    if (tid == 0) {
        int s = 0;
        for (int i = 0; i < TQ; i++) s += si[i];
        g_nposblk[blk] = s;
    }
}

// ============================================================
// Kernel B: reduce k0 partials -> k0n, norms (1024 thr, 4x MLP)
// ============================================================
extern "C" __global__ void kB()
{
    const int k = blockIdx.x;
    const int tid = threadIdx.x;
    const int c = tid & 255;
    const int s = tid >> 8;              // 0..3
    float v = 0.f;
    const int b0 = s * 74, b1 = b0 + 74; // 4*74 = 296
#pragma unroll 4
    for (int b = b0; b < b1; b++)
        v += g_part[(size_t)b * KC + k * C_ + c];

    __shared__ float red[1024];
    red[tid] = v;
    __syncthreads();
    float w = 0.f;
    if (tid < 256) w = red[c] + red[c + 256] + red[c + 512] + red[c + 768];
    __syncthreads();
    if (tid < 256) red[c] = w * w;
    __syncthreads();
    for (int st = 128; st > 0; st >>= 1) {
        if (tid < st) red[tid] += red[tid + st];
        __syncthreads();
    }
    const float ssq = red[0];
    const float inv = 1.0f / fmaxf(sqrtf(ssq), EPSN);
    if (tid < 256) g_k0n[k * C_ + c] = w * inv;
    if (tid == 0)  g_normk[k] = ssq * inv;   // = k0n . k0
}

// ============================================================
// Kernel C: logits + lse; 296 CTAs (2/SM), ring-4 of 16-ch
//   chunks streaming across tile boundaries; shfl epilogue
// ============================================================
extern "C" __global__ void __launch_bounds__(256, 2)
kC(const float* __restrict__ feat)
{
    extern __shared__ float sm[];
    float*    ring = sm;                                 // 4 x [16][260]
    unsigned* sbh  = (unsigned*)(sm + 4 * SLABC * PS);   // [128 ch-pairs][40] half2
    __shared__ float sred[256];

    const int tid  = threadIdx.x;
    const int blk  = blockIdx.x;
    const int lane = tid & 31;
    const int wrp  = tid >> 5;
    const int g    = lane >> 2;
    const int tg   = lane & 3;
    const int qi   = tid & 63;       // staging float4 slot (64 per 256px row)
    const int cr   = tid >> 6;       // staging channel base (0..3)

    // prototypes -> half2 channel-pairs
    for (int i = tid; i < 128 * WS; i += 256) sbh[i] = 0u;
    __syncthreads();
    for (int idx = tid; idx < 128 * K_; idx += 256) {
        const int cp = idx / K_;
        const int k  = idx - cp * K_;
        sbh[cp * WS + k] = pack_h2(g_k0n[k * C_ + 2 * cp],
                                   g_k0n[k * C_ + 2 * cp + 1]);
    }
    __syncthreads();

    auto issue = [&](int m) {
        const int tile = blk + (m >> 4) * NBLK;
        if (tile < NCT) {
            const int s  = m & 15;
            const int c0 = s * SLABC;
            float* buf = ring + (m & 3) * (SLABC * PS);
            const int p0  = tile * CTILE;
            const int b   = p0 >> 16;
            const int hw0 = p0 & 65535;
            const float* fb = feat + (size_t)b * C_ * HW + hw0 + qi * 4;
#pragma unroll
            for (int i = 0; i < 4; i++) {
                const int cl = cr + 4 * i;
                cp16(smem_u32(buf + cl * PS + qi * 4), fb + (size_t)(c0 + cl) * HW);
            }
        }
        cp_commit();
    };

    float acc[2][3][4];
#pragma unroll
    for (int mt = 0; mt < 2; mt++)
#pragma unroll
        for (int nt = 0; nt < 3; nt++)
#pragma unroll
            for (int r = 0; r < 4; r++) acc[mt][nt][r] = 0.f;
    float lacc = 0.f;
    const int Rp = wrp * 32;

    issue(0); issue(1); issue(2);

    int m = 0;
    while (blk + (m >> 4) * NBLK < NCT) {
        __syncthreads();                 // slot (m-1)&3 free everywhere
        issue(m + 3);
        cp_wait<2>();                    // chunk m (and m+1) arrived
        __syncthreads();

        const float* cur = ring + (m & 3) * (SLABC * PS);
        const int s = m & 15;
        {
            unsigned a[2][4];
#pragma unroll
            for (int mt = 0; mt < 2; mt++) {
                const float* base = cur + (2 * tg) * PS + Rp + 16 * mt + g;
                a[mt][0] = pack_h2(base[0],          base[PS]);
                a[mt][1] = pack_h2(base[8],          base[PS + 8]);
                a[mt][2] = pack_h2(base[8 * PS],     base[9 * PS]);
                a[mt][3] = pack_h2(base[8 * PS + 8], base[9 * PS + 8]);
            }
            const int cpi = s * 8;
#pragma unroll
            for (int nt = 0; nt < 3; nt++) {
                unsigned b[2];
                b[0] = sbh[(cpi + tg) * WS + 8 * nt + g];
                b[1] = sbh[(cpi + tg + 4) * WS + 8 * nt + g];
                mma_f16(acc[0][nt], a[0], b);
                mma_f16(acc[1][nt], a[1], b);
            }
        }

        if (s == 15) {
            // ---- register-only epilogue for this tile's 256 pixels ----
            const int tile = blk + (m >> 4) * NBLK;
            const int pb = tile * CTILE + Rp;
            float2 npr[4];
#pragma unroll
            for (int mt = 0; mt < 2; mt++)
#pragma unroll
                for (int rh = 0; rh < 2; rh++)
                    npr[2 * mt + rh] = g_npr[pb + 16 * mt + g + 8 * rh];

            float sume[4];
#pragma unroll
            for (int mt = 0; mt < 2; mt++)
#pragma unroll
                for (int rh = 0; rh < 2; rh++) {
                    const int i = 2 * mt + rh;
                    const float sc = npr[i].y * (1.0f / TAU);
                    float sum = 0.f;
#pragma unroll
                    for (int nt = 0; nt < 3; nt++)
#pragma unroll
                        for (int rl = 0; rl < 2; rl++) {
                            const int col = 8 * nt + 2 * tg + rl;
                            const float v = acc[mt][nt][2 * rh + rl];
                            sum += (col < K_) ? __expf(v * sc) : 0.f;
                        }
                    sume[i] = sum;
                }
#pragma unroll
            for (int i = 0; i < 4; i++) {
                sume[i] += __shfl_xor_sync(0xffffffffu, sume[i], 1);
                sume[i] += __shfl_xor_sync(0xffffffffu, sume[i], 2);
            }
            if (tg == 0) {
#pragma unroll
                for (int i = 0; i < 4; i++)
                    lacc += npr[i].x * __logf(sume[i]);   // |logit| <= ~14.3
            }
#pragma unroll
            for (int mt = 0; mt < 2; mt++)
#pragma unroll
                for (int nt = 0; nt < 3; nt++)
#pragma unroll
                    for (int r = 0; r < 4; r++) acc[mt][nt][r] = 0.f;
        }
        m++;
    }

    // block-reduce lacc
    __syncthreads();
    sred[tid] = lacc;
    __syncthreads();
    for (int st = 128; st > 0; st >>= 1) {
        if (tid < st) sred[tid] += sred[tid + st];
        __syncthreads();
    }
    if (tid == 0) g_lsepart[blk] = sred[0];
}

// ============================================================
// Kernel D: final scalar loss
// ============================================================
extern "C" __global__ void kD(float* __restrict__ out)
{
    __shared__ float red[256];
    __shared__ int   redi[256];
    const int tid = threadIdx.x;

    float a = 0.f;
    for (int i = tid; i < NBLK; i += 256) a += g_lsepart[i];
    float nk = 0.f;
    if (tid < K_) nk = g_normk[tid];
    int np = 0;
    for (int i = tid; i < NBLK; i += 256) np += g_nposblk[i];

    red[tid]  = a - nk * (1.0f / TAU);
    redi[tid] = np;
    __syncthreads();
    for (int s = 128; s > 0; s >>= 1) {
        if (tid < s) { red[tid] += red[tid + s]; redi[tid] += redi[tid + s]; }
        __syncthreads();
    }
    if (tid == 0) out[0] = red[0] / (float)redi[0];
}

// ============================================================
// launch
// ============================================================
extern "C" void kernel_launch(void* const* d_in, const int* in_sizes, int n_in,
                              void* d_out, int out_size)
{
    const float* feat = (const float*)d_in[0];
    const float* gt   = (const float*)d_in[1];
    float* out        = (float*)d_out;

    const int smemA = (2 * C_ * TSA + 2 * 16 * WS / 1 + 2 * K_ * TQ + 256) * 4; // 92928 B
    const int smemC = (4 * SLABC * PS) * 4 + (128 * WS) * 4;                    // 87040 B
    cudaFuncSetAttribute(kA, cudaFuncAttributeMaxDynamicSharedMemorySize, smemA);
    cudaFuncSetAttribute(kC, cudaFuncAttributeMaxDynamicSharedMemorySize, smemC);

    kA<<<NBLK, 256, smemA>>>(feat, gt);
    kB<<<K_, 1024>>>();
    kC<<<NBLK, 256, smemC>>>(feat);
    kD<<<1, 256>>>(out);
}